// round 1
// baseline (speedup 1.0000x reference)
#include <cuda_runtime.h>

// Problem constants
#define Bc 4
#define Cc 64
#define Hc 128
#define Wc 128
#define Oc 64
#define Np 9
#define Hp 130
#define Wp 130
#define NIDX 576   // C*9

// Scratch (device globals; no allocation allowed)
__device__ float g_xp[Bc * Hp * Wp * Cc];   // padded NHWC x  (~16.5 MiB)
__device__ float g_wpm[NIDX * 32];          // offset+mod conv weights, [idx][32ch] (27 used)
__device__ float g_wconv[NIDX * 64];        // final conv weights, [idx][64 out ch]

// ---------------------------------------------------------------------------
// Prep 0: zero the padded buffer (border must be 0; interior overwritten)
// ---------------------------------------------------------------------------
__global__ void zero_xp_kernel(int n) {
    int i = blockIdx.x * blockDim.x + threadIdx.x;
    if (i < n) g_xp[i] = 0.0f;
}

// ---------------------------------------------------------------------------
// Prep 1: NCHW -> padded NHWC transpose via smem tile
// grid: (W/32, H, B*2), block: (32,32). blockIdx.z = b*2 + cblk
// ---------------------------------------------------------------------------
__global__ void transpose_kernel(const float* __restrict__ x) {
    __shared__ float tile[32][33];
    int wblk = blockIdx.x;
    int h    = blockIdx.y;
    int b    = blockIdx.z >> 1;
    int cblk = blockIdx.z & 1;
    int tx = threadIdx.x, ty = threadIdx.y;

    int c = cblk * 32 + ty;
    int w = wblk * 32 + tx;
    tile[ty][tx] = x[((b * Cc + c) * Hc + h) * Wc + w];   // coalesced read
    __syncthreads();

    int c2 = cblk * 32 + tx;
    int w2 = wblk * 32 + ty;
    g_xp[((b * Hp + (h + 1)) * Wp + (w2 + 1)) * Cc + c2] = tile[tx][ty]; // coalesced write
}

// ---------------------------------------------------------------------------
// Prep 2: weight transposes.
//   g_wpm[idx*32+ch]  : ch<18 -> w_p[ch][idx], ch in [18,27) -> w_m[ch-18][idx], else 0
//   g_wconv[idx*64+o] : w_conv[o][idx]
//   (idx = c*9 + ky*3 + kx, matching OIHW flattening)
// ---------------------------------------------------------------------------
__global__ void wprep_kernel(const float* __restrict__ wp,
                             const float* __restrict__ wm,
                             const float* __restrict__ wc) {
    int i = blockIdx.x * blockDim.x + threadIdx.x;
    if (i < NIDX * 32) {
        int idx = i >> 5, ch = i & 31;
        float v = 0.0f;
        if (ch < 18)      v = wp[ch * NIDX + idx];
        else if (ch < 27) v = wm[(ch - 18) * NIDX + idx];
        g_wpm[i] = v;
    }
    if (i < NIDX * 64) {
        int idx = i >> 6, o = i & 63;
        g_wconv[i] = wc[o * NIDX + idx];
    }
}

// ---------------------------------------------------------------------------
// Main fused kernel: 1 block = 8 pixels (along W), 64 threads
// ---------------------------------------------------------------------------
__global__ __launch_bounds__(64) void deform_kernel(
    const float* __restrict__ bp, const float* __restrict__ bm,
    float* __restrict__ out) {

    __shared__ float xs[Cc * 33];                 // 3x10 neighborhood per channel (stride 33)
    __shared__ float cvo[8 * 32];                 // conv outputs: [px][32ch]
    __shared__ int   sidx[72 * 4];                // gather bases per (px,n)
    __shared__ float swt[72 * 4];                 // bilinear*mod weights per (px,n)
    __shared__ __align__(16) float ss[NIDX * 8];  // sampled values: [idx][px]

    const int t  = threadIdx.x;
    const int w0 = blockIdx.x * 8;
    const int h  = blockIdx.y;
    const int b  = blockIdx.z;
    const float* __restrict__ xpb = g_xp + b * (Hp * Wp * Cc);

    // ---- stage 1: load 3x10 x 64ch neighborhood into smem (c = t) ----
    {
        const int c = t;
        #pragma unroll
        for (int ky = 0; ky < 3; ky++) {
            const float* row = xpb + ((h + ky) * Wp + w0) * Cc + c;
            #pragma unroll
            for (int wx = 0; wx < 10; wx++) {
                xs[c * 33 + ky * 10 + wx] = row[wx * Cc];
            }
        }
    }
    __syncthreads();

    // ---- stage 2: offset/mod conv (64 -> 27 channels, 3x3) ----
    const int px  = t >> 3;
    const int ch0 = (t & 7) * 4;
    {
        float a0 = 0.f, a1 = 0.f, a2 = 0.f, a3 = 0.f;
        #pragma unroll 1
        for (int c = 0; c < 64; c++) {
            const float* xr = xs + c * 33 + px;
            const float* wr = g_wpm + c * 9 * 32 + ch0;
            #pragma unroll
            for (int q = 0; q < 9; q++) {
                float xv = xr[(q / 3) * 10 + (q % 3)];
                float4 w4 = *(const float4*)(wr + q * 32);
                a0 += xv * w4.x; a1 += xv * w4.y;
                a2 += xv * w4.z; a3 += xv * w4.w;
            }
        }
        float bb0 = 0.f, bb1 = 0.f, bb2 = 0.f, bb3 = 0.f;
        {
            int ch = ch0;
            bb0 = (ch + 0 < 18) ? bp[ch + 0] : (ch + 0 < 27 ? bm[ch + 0 - 18] : 0.f);
            bb1 = (ch + 1 < 18) ? bp[ch + 1] : (ch + 1 < 27 ? bm[ch + 1 - 18] : 0.f);
            bb2 = (ch + 2 < 18) ? bp[ch + 2] : (ch + 2 < 27 ? bm[ch + 2 - 18] : 0.f);
            bb3 = (ch + 3 < 18) ? bp[ch + 3] : (ch + 3 < 27 ? bm[ch + 3 - 18] : 0.f);
        }
        cvo[px * 32 + ch0 + 0] = a0 + bb0;
        cvo[px * 32 + ch0 + 1] = a1 + bb1;
        cvo[px * 32 + ch0 + 2] = a2 + bb2;
        cvo[px * 32 + ch0 + 3] = a3 + bb3;
    }
    __syncthreads();

    // ---- stage 3: deformable sample coordinates + bilinear weights ----
    for (int task = t; task < 72; task += 64) {
        int tpx = task / 9;
        int n   = task - tpx * 9;
        float offx = cvo[tpx * 32 + n];
        float offy = cvo[tpx * 32 + 9 + n];
        float mz   = cvo[tpx * 32 + 18 + n];
        float mm   = 1.0f / (1.0f + __expf(-mz));   // sigmoid modulation

        int i = n / 3, j = n % 3;
        // p = p0 + pn + offset ; p0_x = h+1, pn_x = i-1  => h + i + offx
        float p_x = (float)(h + i) + offx;
        float p_y = (float)(w0 + tpx + j) + offy;

        float fx = floorf(p_x), fy = floorf(p_y);
        float qltx = fminf(fmaxf(fx,        0.f), 129.f);
        float qlty = fminf(fmaxf(fy,        0.f), 129.f);
        float qrbx = fminf(fmaxf(fx + 1.f,  0.f), 129.f);
        float qrby = fminf(fmaxf(fy + 1.f,  0.f), 129.f);
        float pcx  = fminf(fmaxf(p_x, 0.f), 129.f);
        float pcy  = fminf(fmaxf(p_y, 0.f), 129.f);

        float glt = (1.f + (qltx - pcx)) * (1.f + (qlty - pcy));
        float grb = (1.f - (qrbx - pcx)) * (1.f - (qrby - pcy));
        float glb = (1.f + (qltx - pcx)) * (1.f - (qrby - pcy));
        float grt = (1.f - (qrbx - pcx)) * (1.f + (qlty - pcy));

        int iltx = (int)qltx, ilty = (int)qlty;
        int irbx = (int)qrbx, irby = (int)qrby;
        sidx[task * 4 + 0] = (iltx * Wp + ilty) * Cc;
        sidx[task * 4 + 1] = (irbx * Wp + irby) * Cc;
        sidx[task * 4 + 2] = (iltx * Wp + irby) * Cc;
        sidx[task * 4 + 3] = (irbx * Wp + ilty) * Cc;
        swt[task * 4 + 0] = glt * mm;
        swt[task * 4 + 1] = grb * mm;
        swt[task * 4 + 2] = glb * mm;
        swt[task * 4 + 3] = grt * mm;
    }
    __syncthreads();

    // ---- stage 4: bilinear sampling (c = t), coalesced channel gathers ----
    {
        const int c = t;
        #pragma unroll 1
        for (int tpx = 0; tpx < 8; tpx++) {
            #pragma unroll
            for (int n = 0; n < 9; n++) {
                int task = tpx * 9 + n;
                float v = swt[task * 4 + 0] * xpb[sidx[task * 4 + 0] + c]
                        + swt[task * 4 + 1] * xpb[sidx[task * 4 + 1] + c]
                        + swt[task * 4 + 2] * xpb[sidx[task * 4 + 2] + c]
                        + swt[task * 4 + 3] * xpb[sidx[task * 4 + 3] + c];
                ss[(c * 9 + n) * 8 + tpx] = v;
            }
        }
    }
    __syncthreads();

    // ---- stage 5: final conv: out[o] = sum_idx ss[idx] * w_conv_t[idx][o] ----
    {
        const int o = t;
        float A0 = 0.f, A1 = 0.f, A2 = 0.f, A3 = 0.f;
        float B0 = 0.f, B1 = 0.f, B2 = 0.f, B3 = 0.f;
        const float* wc = g_wconv + o;
        #pragma unroll 8
        for (int idx = 0; idx < NIDX; idx++) {
            float wv = wc[idx * 64];
            float4 sa = *(const float4*)&ss[idx * 8];
            float4 sb = *(const float4*)&ss[idx * 8 + 4];
            A0 += wv * sa.x; A1 += wv * sa.y; A2 += wv * sa.z; A3 += wv * sa.w;
            B0 += wv * sb.x; B1 += wv * sb.y; B2 += wv * sb.z; B3 += wv * sb.w;
        }
        float* op = out + ((b * Oc + o) * Hc + h) * Wc + w0;
        float4 r0 = {A0, A1, A2, A3};
        float4 r1 = {B0, B1, B2, B3};
        *(float4*)(op)     = r0;
        *(float4*)(op + 4) = r1;
    }
}

// ---------------------------------------------------------------------------
extern "C" void kernel_launch(void* const* d_in, const int* in_sizes, int n_in,
                              void* d_out, int out_size) {
    const float* x      = (const float*)d_in[0];
    const float* w_p    = (const float*)d_in[1];
    const float* b_p    = (const float*)d_in[2];
    const float* w_m    = (const float*)d_in[3];
    const float* b_m    = (const float*)d_in[4];
    const float* w_conv = (const float*)d_in[5];
    float* out = (float*)d_out;

    int nxp = Bc * Hp * Wp * Cc;
    zero_xp_kernel<<<(nxp + 255) / 256, 256>>>(nxp);
    transpose_kernel<<<dim3(4, 128, 8), dim3(32, 32)>>>(x);
    wprep_kernel<<<(NIDX * 64 + 255) / 256, 256>>>(w_p, w_m, w_conv);
    deform_kernel<<<dim3(16, 128, 4), 64>>>(b_p, b_m, out);
}

// round 3
// speedup vs baseline: 2.7525x; 2.7525x over previous
#include <cuda_runtime.h>
#include <cstdint>

#define Bc 4
#define Cc 64
#define Hc 128
#define Wc 128
#define Oc 64
#define Hp 130
#define Wp 130

// Device scratch (no allocation allowed)
__device__ float g_xp[Bc * Hp * Wp * Cc];   // padded NHWC x (~16.5 MiB)
__device__ float g_wb2[9 * 32 * 64];        // stage-2 B: [tap q][n(32,27 used)][c] tf32
__device__ float g_wb5[9 * 64 * 64];        // stage-5 B: [sample n][o][c] tf32

__device__ __forceinline__ float to_tf32(float x) {
    float r; asm("cvt.rna.tf32.f32 %0, %1;" : "=f"(r) : "f"(x)); return r;
}

// m16n8k8 tf32 MMA: C(16x8) += A(16x8,row) * B(8x8,col)
__device__ __forceinline__ void mma8(float* c, const uint32_t* a, uint32_t b0, uint32_t b1) {
    asm volatile("mma.sync.aligned.m16n8k8.row.col.f32.tf32.tf32.f32 "
        "{%0,%1,%2,%3}, {%4,%5,%6,%7}, {%8,%9}, {%0,%1,%2,%3};"
        : "+f"(c[0]), "+f"(c[1]), "+f"(c[2]), "+f"(c[3])
        : "r"(a[0]), "r"(a[1]), "r"(a[2]), "r"(a[3]), "r"(b0), "r"(b1));
}

// smem layout (bytes). As region reused as C-staging after GEMMs.
#define SM_A     0          /* 128 x 68 floats = 34816  (also Cs2 32x132, Cs5 64x132) */
#define SM_B     34816      /* 64 x 68 floats  = 17408 */
#define SM_SWT   52224      /* float4[128*9]   = 18432 */
#define SM_SIDX  70656      /* int4[128*9]     = 18432 */
#define SM_TOTAL 89088

// ---------------------------------------------------------------------------
// Prep kernels
// ---------------------------------------------------------------------------
__global__ void border_kernel() {
    int i = blockIdx.x * blockDim.x + threadIdx.x;
    const int per = (2 * 130 + 2 * 128) * 64;  // 33024
    if (i >= Bc * per) return;
    int b = i / per, r = i % per;
    int base = b * Hp * Wp * Cc;
    if (r < 130 * 64)            g_xp[base + r] = 0.f;
    else if (r < 2 * 130 * 64)   g_xp[base + 129 * Wp * Cc + (r - 130 * 64)] = 0.f;
    else {
        int t = r - 2 * 130 * 64;
        int which = t / (128 * 64);
        int u = t % (128 * 64);
        int rr = u / 64, c = u % 64;
        int w = which ? 129 : 0;
        g_xp[base + (rr + 1) * Wp * Cc + w * Cc + c] = 0.f;
    }
}

__global__ void transpose_kernel(const float* __restrict__ x) {
    __shared__ float tile[32][33];
    int wblk = blockIdx.x, h = blockIdx.y;
    int b = blockIdx.z >> 1, cblk = blockIdx.z & 1;
    int tx = threadIdx.x, ty = threadIdx.y;
    int c = cblk * 32 + ty, w = wblk * 32 + tx;
    tile[ty][tx] = x[((b * Cc + c) * Hc + h) * Wc + w];
    __syncthreads();
    int c2 = cblk * 32 + tx, w2 = wblk * 32 + ty;
    g_xp[((b * Hp + (h + 1)) * Wp + (w2 + 1)) * Cc + c2] = tile[tx][ty];
}

__global__ void wprep_kernel(const float* __restrict__ wp,
                             const float* __restrict__ wm,
                             const float* __restrict__ wc) {
    int i = blockIdx.x * blockDim.x + threadIdx.x;
    if (i < 9 * 32 * 64) {
        int q = i >> 11, rem = i & 2047, r = rem >> 6, c = rem & 63;
        float v = 0.f;
        if (r < 18)      v = wp[r * 576 + c * 9 + q];
        else if (r < 27) v = wm[(r - 18) * 576 + c * 9 + q];
        g_wb2[i] = to_tf32(v);
    }
    if (i < 9 * 64 * 64) {
        int n = i >> 12, rem = i & 4095, o = rem >> 6, c = rem & 63;
        g_wb5[i] = to_tf32(wc[o * 576 + c * 9 + n]);
    }
}

// ---------------------------------------------------------------------------
// Main fused kernel: 1 block = one (b,h) row of 128 pixels, 256 threads
// ---------------------------------------------------------------------------
__global__ __launch_bounds__(256, 2) void deform_kernel(
    const float* __restrict__ bp, const float* __restrict__ bm,
    float* __restrict__ out) {

    extern __shared__ char sm[];
    float*    As  = (float*)(sm + SM_A);
    uint32_t* AsU = (uint32_t*)(sm + SM_A);
    float*    Bs  = (float*)(sm + SM_B);
    uint32_t* BsU = (uint32_t*)(sm + SM_B);
    float4*   swt4  = (float4*)(sm + SM_SWT);
    int4*     sidx4 = (int4*)(sm + SM_SIDX);
    float*    Cs  = (float*)(sm + SM_A);   // C staging (overlays As)

    const int tid = threadIdx.x;
    const int warp = tid >> 5, lane = tid & 31;
    const int g = lane >> 2, t4 = lane & 3;
    const int px0 = warp * 16;
    const int h = blockIdx.x, b = blockIdx.y;
    const float* __restrict__ xpb = g_xp + b * (Hp * Wp * Cc);

    // ================= Stage 2: offset/mod conv GEMM (M=128,N=32,K=9x64) =====
    float C2[4][4];
    #pragma unroll
    for (int nt = 0; nt < 4; nt++)
        #pragma unroll
        for (int r = 0; r < 4; r++) C2[nt][r] = 0.f;

    for (int q = 0; q < 9; q++) {
        const int qy = q / 3, qx = q % 3;
        // A tile: [128 px][64 c] <- contiguous NHWC slice (tf32-converted)
        const float* src = xpb + ((h + qy) * Wp + qx) * Cc;
        #pragma unroll
        for (int r = 0; r < 8; r++) {
            int f = r * 256 + tid;           // 2048 float4
            int px = f >> 4, cg = f & 15;
            float4 v = *(const float4*)(src + px * 64 + cg * 4);
            float4 tv;
            tv.x = to_tf32(v.x); tv.y = to_tf32(v.y);
            tv.z = to_tf32(v.z); tv.w = to_tf32(v.w);
            *(float4*)(As + px * 68 + cg * 4) = tv;
        }
        // B tile: [32 n][64 c]
        #pragma unroll
        for (int r = 0; r < 2; r++) {
            int f = r * 256 + tid;           // 512 float4
            int n = f >> 4, cg = f & 15;
            *(float4*)(Bs + n * 68 + cg * 4) =
                *(const float4*)(g_wb2 + (q * 32 + n) * 64 + cg * 4);
        }
        __syncthreads();
        #pragma unroll
        for (int ks = 0; ks < 8; ks++) {
            const int k0 = ks * 8;
            uint32_t a[4];
            a[0] = AsU[(px0 + g) * 68 + k0 + t4];
            a[1] = AsU[(px0 + 8 + g) * 68 + k0 + t4];
            a[2] = AsU[(px0 + g) * 68 + k0 + t4 + 4];
            a[3] = AsU[(px0 + 8 + g) * 68 + k0 + t4 + 4];
            #pragma unroll
            for (int nt = 0; nt < 4; nt++) {
                uint32_t b0 = BsU[(nt * 8 + g) * 68 + k0 + t4];
                uint32_t b1 = BsU[(nt * 8 + g) * 68 + k0 + t4 + 4];
                mma8(C2[nt], a, b0, b1);
            }
        }
        __syncthreads();
    }
    // stage C2 -> smem  [n][132 + px]
    #pragma unroll
    for (int nt = 0; nt < 4; nt++) {
        int n = nt * 8 + 2 * t4;
        Cs[n * 132 + px0 + g]           = C2[nt][0];
        Cs[(n + 1) * 132 + px0 + g]     = C2[nt][1];
        Cs[n * 132 + px0 + 8 + g]       = C2[nt][2];
        Cs[(n + 1) * 132 + px0 + 8 + g] = C2[nt][3];
    }
    __syncthreads();

    // ============ Offsets: bilinear taps + weights (threads 0..127) ============
    if (tid < 128) {
        const int px = tid;
        #pragma unroll
        for (int n = 0; n < 9; n++) {
            float offx = Cs[n * 132 + px]        + bp[n];
            float offy = Cs[(9 + n) * 132 + px]  + bp[9 + n];
            float mz   = Cs[(18 + n) * 132 + px] + bm[n];
            float mm = 1.0f / (1.0f + __expf(-mz));
            int i = n / 3, jj = n % 3;
            float p_x = (float)(h + i) + offx;
            float p_y = (float)(px + jj) + offy;
            float fx = floorf(p_x), fy = floorf(p_y);
            float qltx = fminf(fmaxf(fx,       0.f), 129.f);
            float qlty = fminf(fmaxf(fy,       0.f), 129.f);
            float qrbx = fminf(fmaxf(fx + 1.f, 0.f), 129.f);
            float qrby = fminf(fmaxf(fy + 1.f, 0.f), 129.f);
            float pcx  = fminf(fmaxf(p_x, 0.f), 129.f);
            float pcy  = fminf(fmaxf(p_y, 0.f), 129.f);
            float glt = (1.f + (qltx - pcx)) * (1.f + (qlty - pcy));
            float grb = (1.f - (qrbx - pcx)) * (1.f - (qrby - pcy));
            float glb = (1.f + (qltx - pcx)) * (1.f - (qrby - pcy));
            float grt = (1.f - (qrbx - pcx)) * (1.f + (qlty - pcy));
            int iltx = (int)qltx, ilty = (int)qlty;
            int irbx = (int)qrbx, irby = (int)qrby;
            int4 qi;
            qi.x = (iltx * Wp + ilty) * Cc;
            qi.y = (irbx * Wp + irby) * Cc;
            qi.z = (iltx * Wp + irby) * Cc;
            qi.w = (irbx * Wp + ilty) * Cc;
            float4 wv;
            wv.x = glt * mm; wv.y = grb * mm; wv.z = glb * mm; wv.w = grt * mm;
            sidx4[px * 9 + n] = qi;
            swt4[px * 9 + n]  = wv;
        }
    }
    __syncthreads();

    // ============ Stage 5: sample + GEMM (M=128,N=64,K=9x64) ============
    float C5[8][4];
    #pragma unroll
    for (int nt = 0; nt < 8; nt++)
        #pragma unroll
        for (int r = 0; r < 4; r++) C5[nt][r] = 0.f;

    for (int n = 0; n < 9; n++) {
        // A tile: bilinear samples, [128 px][64 c]
        #pragma unroll 2
        for (int k = 0; k < 16; k++) {
            int px = px0 + k;
            int4   q4 = sidx4[px * 9 + n];
            float4 w4 = swt4[px * 9 + n];
            #pragma unroll
            for (int chalf = 0; chalf < 2; chalf++) {
                int c = chalf * 32 + lane;
                const float* xb = xpb + c;
                float v = w4.x * xb[q4.x] + w4.y * xb[q4.y]
                        + w4.z * xb[q4.z] + w4.w * xb[q4.w];
                As[px * 68 + c] = to_tf32(v);
            }
        }
        // B tile: [64 o][64 c]
        #pragma unroll
        for (int r = 0; r < 4; r++) {
            int f = r * 256 + tid;           // 1024 float4
            int o = f >> 4, cg = f & 15;
            *(float4*)(Bs + o * 68 + cg * 4) =
                *(const float4*)(g_wb5 + (n * 64 + o) * 64 + cg * 4);
        }
        __syncthreads();
        #pragma unroll
        for (int ks = 0; ks < 8; ks++) {
            const int k0 = ks * 8;
            uint32_t a[4];
            a[0] = AsU[(px0 + g) * 68 + k0 + t4];
            a[1] = AsU[(px0 + 8 + g) * 68 + k0 + t4];
            a[2] = AsU[(px0 + g) * 68 + k0 + t4 + 4];
            a[3] = AsU[(px0 + 8 + g) * 68 + k0 + t4 + 4];
            #pragma unroll
            for (int nt = 0; nt < 8; nt++) {
                uint32_t b0 = BsU[(nt * 8 + g) * 68 + k0 + t4];
                uint32_t b1 = BsU[(nt * 8 + g) * 68 + k0 + t4 + 4];
                mma8(C5[nt], a, b0, b1);
            }
        }
        __syncthreads();
    }

    // stage C5 -> smem [o][132 + px]
    #pragma unroll
    for (int nt = 0; nt < 8; nt++) {
        int o = nt * 8 + 2 * t4;
        Cs[o * 132 + px0 + g]           = C5[nt][0];
        Cs[(o + 1) * 132 + px0 + g]     = C5[nt][1];
        Cs[o * 132 + px0 + 8 + g]       = C5[nt][2];
        Cs[(o + 1) * 132 + px0 + 8 + g] = C5[nt][3];
    }
    __syncthreads();

    // coalesced NCHW store
    float* __restrict__ ob = out + (b * Oc * Hc + h) * Wc;
    #pragma unroll
    for (int r = 0; r < 32; r++) {
        int f = r * 256 + tid;               // 8192 values
        int o = f >> 7, px = f & 127;
        ob[o * (Hc * Wc) + px] = Cs[o * 132 + px];
    }
}

// ---------------------------------------------------------------------------
extern "C" void kernel_launch(void* const* d_in, const int* in_sizes, int n_in,
                              void* d_out, int out_size) {
    const float* x      = (const float*)d_in[0];
    const float* w_p    = (const float*)d_in[1];
    const float* b_p    = (const float*)d_in[2];
    const float* w_m    = (const float*)d_in[3];
    const float* b_m    = (const float*)d_in[4];
    const float* w_conv = (const float*)d_in[5];
    float* out = (float*)d_out;

    cudaFuncSetAttribute(deform_kernel,
                         cudaFuncAttributeMaxDynamicSharedMemorySize, SM_TOTAL);

    int nb = Bc * (2 * 130 + 2 * 128) * 64;
    border_kernel<<<(nb + 255) / 256, 256>>>();
    transpose_kernel<<<dim3(4, 128, 8), dim3(32, 32)>>>(x);
    wprep_kernel<<<(9 * 64 * 64 + 255) / 256, 256>>>(w_p, w_m, w_conv);
    deform_kernel<<<dim3(Hc, Bc), 256, SM_TOTAL>>>(b_p, b_m, out);
}

// round 4
// speedup vs baseline: 2.9541x; 1.0732x over previous
#include <cuda_runtime.h>
#include <cstdint>

#define Bc 4
#define Cc 64
#define Hc 128
#define Wc 128
#define Oc 64
#define Hp 130
#define Wp 130

// Device scratch (no allocation allowed)
__device__ float g_xp[Bc * Hp * Wp * Cc];   // padded NHWC x (~16.5 MiB)
__device__ float g_wb2[9 * 32 * 64];        // stage-2 B: [tap q][n 32][c 64] swizzled tf32
__device__ float g_wb5[9 * 64 * 64];        // stage-5 B: [sample n][o 64][c 64] swizzled tf32

__device__ __forceinline__ float to_tf32(float x) {
    float r; asm("cvt.rna.tf32.f32 %0, %1;" : "=f"(r) : "f"(x)); return r;
}
__device__ __forceinline__ uint32_t smem_u32(const void* p) {
    uint32_t a;
    asm("{ .reg .u64 t; cvta.to.shared.u64 t, %1; cvt.u32.u64 %0, t; }" : "=r"(a) : "l"(p));
    return a;
}
__device__ __forceinline__ void cp16(uint32_t dst, const void* src) {
    asm volatile("cp.async.ca.shared.global [%0], [%1], 16;" :: "r"(dst), "l"(src));
}

// m16n8k8 tf32 MMA
__device__ __forceinline__ void mma8(float* c, const uint32_t* a, uint32_t b0, uint32_t b1) {
    asm volatile("mma.sync.aligned.m16n8k8.row.col.f32.tf32.tf32.f32 "
        "{%0,%1,%2,%3}, {%4,%5,%6,%7}, {%8,%9}, {%0,%1,%2,%3};"
        : "+f"(c[0]), "+f"(c[1]), "+f"(c[2]), "+f"(c[3])
        : "r"(a[0]), "r"(a[1]), "r"(a[2]), "r"(a[3]), "r"(b0), "r"(b1));
}

// smem layout (bytes)
#define SM_A     0          /* 128x64 swizzled floats = 32768; also C2-staging + C5-staging */
#define SM_B     32768      /* 64x64 swizzled floats = 16384 */
#define SM_SWT   49152      /* float4[128*9] = 18432 */
#define SM_SIDX  67584      /* int[128*9] = 4608 */
#define SM_TOTAL 72192

// ---------------------------------------------------------------------------
// Prep kernels
// ---------------------------------------------------------------------------
__global__ void prep_kernel(const float* __restrict__ wp,
                            const float* __restrict__ wm,
                            const float* __restrict__ wc) {
    int i = blockIdx.x * blockDim.x + threadIdx.x;
    // border zeroing of g_xp
    const int per = (2 * 130 + 2 * 128) * 64;  // 33024
    if (i < Bc * per) {
        int b = i / per, r = i % per;
        int base = b * Hp * Wp * Cc;
        if (r < 130 * 64)            g_xp[base + r] = 0.f;
        else if (r < 2 * 130 * 64)   g_xp[base + 129 * Wp * Cc + (r - 130 * 64)] = 0.f;
        else {
            int t = r - 2 * 130 * 64;
            int which = t / (128 * 64);
            int u = t % (128 * 64);
            int rr = u / 64, c = u % 64;
            int w = which ? 129 : 0;
            g_xp[base + (rr + 1) * Wp * Cc + w * Cc + c] = 0.f;
        }
    }
    // stage-2 weights, swizzled
    if (i < 9 * 32 * 64) {
        int q = i >> 11, rem = i & 2047, n = rem >> 6, c = rem & 63;
        float v = 0.f;
        if (n < 18)      v = wp[n * 576 + c * 9 + q];
        else if (n < 27) v = wm[(n - 18) * 576 + c * 9 + q];
        g_wb2[q * 2048 + n * 64 + (c ^ ((n & 7) << 2))] = to_tf32(v);
    }
    // stage-5 weights, swizzled
    if (i < 9 * 64 * 64) {
        int n = i >> 12, rem = i & 4095, o = rem >> 6, c = rem & 63;
        g_wb5[n * 4096 + o * 64 + (c ^ ((o & 7) << 2))] = to_tf32(wc[o * 576 + c * 9 + n]);
    }
}

__global__ void transpose_kernel(const float* __restrict__ x) {
    __shared__ float tile[32][33];
    int wblk = blockIdx.x, h = blockIdx.y;
    int b = blockIdx.z >> 1, cblk = blockIdx.z & 1;
    int tx = threadIdx.x, ty = threadIdx.y;
    int c = cblk * 32 + ty, w = wblk * 32 + tx;
    tile[ty][tx] = x[((b * Cc + c) * Hc + h) * Wc + w];
    __syncthreads();
    int c2 = cblk * 32 + tx, w2 = wblk * 32 + ty;
    g_xp[((b * Hp + (h + 1)) * Wp + (w2 + 1)) * Cc + c2] = tile[tx][ty];
}

// ---------------------------------------------------------------------------
// Main fused kernel: 1 block = one (b,h) row of 128 pixels, 256 threads
// Warp tiling: mg = warp>>1 (M-group of 32 px), nh = warp&1 (N-half)
// ---------------------------------------------------------------------------
__global__ __launch_bounds__(256, 3) void deform_kernel(
    const float* __restrict__ bp, const float* __restrict__ bm,
    float* __restrict__ out) {

    extern __shared__ char sm[];
    float*    As   = (float*)(sm + SM_A);
    uint32_t* AsU  = (uint32_t*)(sm + SM_A);
    float*    Bs   = (float*)(sm + SM_B);
    uint32_t* BsU  = (uint32_t*)(sm + SM_B);
    float4*   swt4 = (float4*)(sm + SM_SWT);
    int*      sidx = (int*)(sm + SM_SIDX);
    float*    Cst  = (float*)(sm + SM_A);   // staging overlay

    const uint32_t smbA = smem_u32(sm) + SM_A;
    const int tid = threadIdx.x;
    const int warp = tid >> 5, lane = tid & 31;
    const int g = lane >> 2, t4 = lane & 3;
    const int mg = warp >> 1, nh = warp & 1;
    const int px0 = mg * 32;
    const int h = blockIdx.x, b = blockIdx.y;
    const float* __restrict__ xpb = g_xp + b * (Hp * Wp * Cc);

    // ================= Stage 2: offset/mod conv GEMM (M=128,N=32,K=9x64) =====
    float C2[2][2][4];
    #pragma unroll
    for (int mt = 0; mt < 2; mt++)
        #pragma unroll
        for (int nt = 0; nt < 2; nt++)
            #pragma unroll
            for (int r = 0; r < 4; r++) C2[mt][nt][r] = 0.f;

    for (int q = 0; q < 9; q++) {
        const int qy = q / 3, qx = q % 3;
        // A tile: raw fp32 via cp.async (tf32 truncation in MMA), swizzled dst
        const float* src = xpb + ((h + qy) * Wp + qx) * Cc;
        #pragma unroll
        for (int r = 0; r < 8; r++) {
            int f = r * 256 + tid;           // 2048 float4
            int px = f >> 4, cg = f & 15;
            uint32_t dst = smbA + (px * 64 + 4 * (cg ^ (px & 7))) * 4;
            cp16(dst, src + px * 64 + cg * 4);
        }
        asm volatile("cp.async.commit_group;");
        // B tile: 32x64 swizzled, straight copy
        #pragma unroll
        for (int r = 0; r < 2; r++) {
            int f = r * 256 + tid;
            ((float4*)Bs)[f] = ((const float4*)(g_wb2 + q * 2048))[f];
        }
        asm volatile("cp.async.wait_group 0;");
        __syncthreads();
        #pragma unroll
        for (int ks = 0; ks < 8; ks++) {
            const int k0 = ks * 8;
            const int sc0 = (k0 + t4) ^ (g << 2);
            const int sc1 = (k0 + t4 + 4) ^ (g << 2);
            #pragma unroll
            for (int mt = 0; mt < 2; mt++) {
                uint32_t a[4];
                int r0 = px0 + mt * 16 + g;
                a[0] = AsU[r0 * 64 + sc0];
                a[1] = AsU[(r0 + 8) * 64 + sc0];
                a[2] = AsU[r0 * 64 + sc1];
                a[3] = AsU[(r0 + 8) * 64 + sc1];
                #pragma unroll
                for (int nt = 0; nt < 2; nt++) {
                    int n = (nh * 2 + nt) * 8 + g;
                    uint32_t b0 = BsU[n * 64 + sc0];
                    uint32_t b1 = BsU[n * 64 + sc1];
                    mma8(C2[mt][nt], a, b0, b1);
                }
            }
        }
        __syncthreads();
    }
    // stage C2 -> smem tmp [n][132 stride] (overlays As)
    #pragma unroll
    for (int mt = 0; mt < 2; mt++)
        #pragma unroll
        for (int nt = 0; nt < 2; nt++) {
            int n = (nh * 2 + nt) * 8 + 2 * t4;
            int px = px0 + mt * 16 + g;
            if (n < 27)     { Cst[n * 132 + px]       = C2[mt][nt][0];
                              Cst[n * 132 + px + 8]   = C2[mt][nt][2]; }
            if (n + 1 < 27) { Cst[(n + 1) * 132 + px]     = C2[mt][nt][1];
                              Cst[(n + 1) * 132 + px + 8] = C2[mt][nt][3]; }
        }
    __syncthreads();

    // ============ Offsets: bilinear taps + weights (threads 0..127) ============
    if (tid < 128) {
        const int px = tid;
        #pragma unroll
        for (int n = 0; n < 9; n++) {
            float offx = Cst[n * 132 + px]        + bp[n];
            float offy = Cst[(9 + n) * 132 + px]  + bp[9 + n];
            float mz   = Cst[(18 + n) * 132 + px] + bm[n];
            float mm = 1.0f / (1.0f + __expf(-mz));
            int i = n / 3, jj = n % 3;
            float p_x = (float)(h + i) + offx;
            float p_y = (float)(px + jj) + offy;
            float fx = floorf(p_x), fy = floorf(p_y);
            float qltx = fminf(fmaxf(fx,       0.f), 129.f);
            float qlty = fminf(fmaxf(fy,       0.f), 129.f);
            float qrbx = fminf(fmaxf(fx + 1.f, 0.f), 129.f);
            float qrby = fminf(fmaxf(fy + 1.f, 0.f), 129.f);
            float pcx  = fminf(fmaxf(p_x, 0.f), 129.f);
            float pcy  = fminf(fmaxf(p_y, 0.f), 129.f);
            float glt = (1.f + (qltx - pcx)) * (1.f + (qlty - pcy));
            float grb = (1.f - (qrbx - pcx)) * (1.f - (qrby - pcy));
            float glb = (1.f + (qltx - pcx)) * (1.f - (qrby - pcy));
            float grt = (1.f - (qrbx - pcx)) * (1.f + (qlty - pcy));
            int iltx = (int)qltx, ilty = (int)qlty;
            int irbx = (int)qrbx, irby = (int)qrby;
            int base = (iltx * Wp + ilty) * Cc;
            int pack = base | ((irbx - iltx) << 24) | ((irby - ilty) << 25);
            float4 wv;
            wv.x = glt * mm; wv.y = grb * mm; wv.z = glb * mm; wv.w = grt * mm;
            sidx[px * 9 + n] = pack;
            swt4[px * 9 + n] = wv;
        }
    }
    __syncthreads();

    // ============ Stage 5: sample + GEMM (M=128,N=64,K=9x64) ============
    float C5[2][4][4];
    #pragma unroll
    for (int mt = 0; mt < 2; mt++)
        #pragma unroll
        for (int nt = 0; nt < 4; nt++)
            #pragma unroll
            for (int r = 0; r < 4; r++) C5[mt][nt][r] = 0.f;

    const int n0 = nh * 32;
    for (int n = 0; n < 9; n++) {
        // A tile: bilinear samples, swizzled [128 px][64 c]
        #pragma unroll 4
        for (int k = 0; k < 16; k++) {
            int px = warp * 16 + k;
            int si = sidx[px * 9 + n];
            float4 w4 = swt4[px * 9 + n];
            int base = si & 0xFFFFFF;
            int dx = (si & (1 << 24)) ? (Wp * Cc) : 0;
            int dy = (si & (1 << 25)) ? Cc : 0;
            #pragma unroll
            for (int chalf = 0; chalf < 2; chalf++) {
                int c = chalf * 32 + lane;
                const float* xb = xpb + c;
                float v = w4.x * xb[base] + w4.y * xb[base + dx + dy]
                        + w4.z * xb[base + dy] + w4.w * xb[base + dx];
                As[px * 64 + (c ^ ((px & 7) << 2))] = to_tf32(v);
            }
        }
        // B tile: 64x64 swizzled, straight copy
        #pragma unroll
        for (int r = 0; r < 4; r++) {
            int f = r * 256 + tid;
            ((float4*)Bs)[f] = ((const float4*)(g_wb5 + n * 4096))[f];
        }
        __syncthreads();
        #pragma unroll
        for (int ks = 0; ks < 8; ks++) {
            const int k0 = ks * 8;
            const int sc0 = (k0 + t4) ^ (g << 2);
            const int sc1 = (k0 + t4 + 4) ^ (g << 2);
            #pragma unroll
            for (int mt = 0; mt < 2; mt++) {
                uint32_t a[4];
                int r0 = px0 + mt * 16 + g;
                a[0] = AsU[r0 * 64 + sc0];
                a[1] = AsU[(r0 + 8) * 64 + sc0];
                a[2] = AsU[r0 * 64 + sc1];
                a[3] = AsU[(r0 + 8) * 64 + sc1];
                #pragma unroll
                for (int nt = 0; nt < 4; nt++) {
                    int nn = n0 + nt * 8 + g;
                    uint32_t b0 = BsU[nn * 64 + sc0];
                    uint32_t b1 = BsU[nn * 64 + sc1];
                    mma8(C5[mt][nt], a, b0, b1);
                }
            }
        }
        __syncthreads();
    }

    // stage C5 -> smem [o][128 stride] (overlays As)
    #pragma unroll
    for (int mt = 0; mt < 2; mt++)
        #pragma unroll
        for (int nt = 0; nt < 4; nt++) {
            int o = n0 + nt * 8 + 2 * t4;
            int px = px0 + mt * 16 + g;
            Cst[o * 128 + px]           = C5[mt][nt][0];
            Cst[(o + 1) * 128 + px]     = C5[mt][nt][1];
            Cst[o * 128 + px + 8]       = C5[mt][nt][2];
            Cst[(o + 1) * 128 + px + 8] = C5[mt][nt][3];
        }
    __syncthreads();

    // coalesced NCHW store
    float* __restrict__ ob = out + (b * Oc * Hc + h) * Wc;
    #pragma unroll
    for (int r = 0; r < 32; r++) {
        int f = r * 256 + tid;
        int o = f >> 7, px = f & 127;
        ob[o * (Hc * Wc) + px] = Cst[o * 128 + px];
    }
}

// ---------------------------------------------------------------------------
extern "C" void kernel_launch(void* const* d_in, const int* in_sizes, int n_in,
                              void* d_out, int out_size) {
    const float* x      = (const float*)d_in[0];
    const float* w_p    = (const float*)d_in[1];
    const float* b_p    = (const float*)d_in[2];
    const float* w_m    = (const float*)d_in[3];
    const float* b_m    = (const float*)d_in[4];
    const float* w_conv = (const float*)d_in[5];
    float* out = (float*)d_out;

    cudaFuncSetAttribute(deform_kernel,
                         cudaFuncAttributeMaxDynamicSharedMemorySize, SM_TOTAL);

    int nprep = Bc * (2 * 130 + 2 * 128) * 64;   // border count dominates
    prep_kernel<<<(nprep + 255) / 256, 256>>>(w_p, w_m, w_conv);
    transpose_kernel<<<dim3(4, 128, 8), dim3(32, 32)>>>(x);
    deform_kernel<<<dim3(Hc, Bc), 256, SM_TOTAL>>>(b_p, b_m, out);
}

// round 9
// speedup vs baseline: 3.7959x; 1.2850x over previous
#include <cuda_runtime.h>
#include <cstdint>

#define Bc 4
#define Cc 64
#define Hc 128
#define Wc 128
#define Oc 64
#define Hp 130
#define Wp 130

// Device scratch (no allocation allowed)
__device__ float g_xp[Bc * Hp * Wp * Cc];   // padded NHWC x (~16.5 MiB)
__device__ float g_wb2[9 * 32 * 64];        // stage-2 B: [tap q][n 32][c 64] swizzled tf32
__device__ float g_wb5[9 * 64 * 64];        // stage-5 B: [sample n][o 64][c 64] swizzled tf32

__device__ __forceinline__ float to_tf32(float x) {
    float r; asm("cvt.rna.tf32.f32 %0, %1;" : "=f"(r) : "f"(x)); return r;
}
__device__ __forceinline__ uint32_t smem_u32(const void* p) {
    uint32_t a;
    asm("{ .reg .u64 t; cvta.to.shared.u64 t, %1; cvt.u32.u64 %0, t; }" : "=r"(a) : "l"(p));
    return a;
}
__device__ __forceinline__ void cp16(uint32_t dst, const void* src) {
    asm volatile("cp.async.ca.shared.global [%0], [%1], 16;" :: "r"(dst), "l"(src));
}

// m16n8k8 tf32 MMA
__device__ __forceinline__ void mma8(float* c, const uint32_t* a, uint32_t b0, uint32_t b1) {
    asm volatile("mma.sync.aligned.m16n8k8.row.col.f32.tf32.tf32.f32 "
        "{%0,%1,%2,%3}, {%4,%5,%6,%7}, {%8,%9}, {%0,%1,%2,%3};"
        : "+f"(c[0]), "+f"(c[1]), "+f"(c[2]), "+f"(c[3])
        : "r"(a[0]), "r"(a[1]), "r"(a[2]), "r"(a[3]), "r"(b0), "r"(b1));
}

// smem layout (bytes)
#define SM_A     0          /* 128x64 swizzled floats = 32768; also C staging overlay */
#define SM_B     32768      /* 64x64 swizzled floats = 16384 */
#define SM_SWT   49152      /* float4[128*9] = 18432 */
#define SM_SIDX  67584      /* int[128*9] = 4608 */
#define SM_TOTAL 72192

// ---------------------------------------------------------------------------
// Prep: border zero + weight transposes (fused)
// ---------------------------------------------------------------------------
__global__ void prep_kernel(const float* __restrict__ wp,
                            const float* __restrict__ wm,
                            const float* __restrict__ wc) {
    int i = blockIdx.x * blockDim.x + threadIdx.x;
    const int per = (2 * 130 + 2 * 128) * 64;  // 33024
    if (i < Bc * per) {
        int b = i / per, r = i % per;
        int base = b * Hp * Wp * Cc;
        if (r < 130 * 64)            g_xp[base + r] = 0.f;
        else if (r < 2 * 130 * 64)   g_xp[base + 129 * Wp * Cc + (r - 130 * 64)] = 0.f;
        else {
            int t = r - 2 * 130 * 64;
            int which = t / (128 * 64);
            int u = t % (128 * 64);
            int rr = u / 64, c = u % 64;
            int w = which ? 129 : 0;
            g_xp[base + (rr + 1) * Wp * Cc + w * Cc + c] = 0.f;
        }
    }
    if (i < 9 * 32 * 64) {
        int q = i >> 11, rem = i & 2047, n = rem >> 6, c = rem & 63;
        float v = 0.f;
        if (n < 18)      v = wp[n * 576 + c * 9 + q];
        else if (n < 27) v = wm[(n - 18) * 576 + c * 9 + q];
        g_wb2[q * 2048 + n * 64 + (c ^ ((n & 7) << 2))] = to_tf32(v);
    }
    if (i < 9 * 64 * 64) {
        int n = i >> 12, rem = i & 4095, o = rem >> 6, c = rem & 63;
        g_wb5[n * 4096 + o * 64 + (c ^ ((o & 7) << 2))] = to_tf32(wc[o * 576 + c * 9 + n]);
    }
}

// ---------------------------------------------------------------------------
// NCHW -> padded NHWC transpose. grid (4,128,8), block 256.
// blockIdx.z = b*2 + cblk; each block: 32 w x 32 c tile.
// ---------------------------------------------------------------------------
__global__ __launch_bounds__(256) void transpose_kernel(const float* __restrict__ x) {
    __shared__ float tile[32][33];
    int wblk = blockIdx.x, h = blockIdx.y;
    int b = blockIdx.z >> 1, cblk = blockIdx.z & 1;
    int l = threadIdx.x;
    int tx = l & 31, ty = l >> 5;            // 32 x 8
    #pragma unroll
    for (int r = 0; r < 4; r++) {
        int c = ty + r * 8;
        tile[c][tx] = x[((b * Cc + cblk * 32 + c) * Hc + h) * Wc + wblk * 32 + tx];
    }
    __syncthreads();
    // write: one float4 per thread: j = channel quad (0..7), w2 = w pos (0..31)
    int j = l & 7, w2 = l >> 3;
    float4 v;
    v.x = tile[j * 4 + 0][w2];
    v.y = tile[j * 4 + 1][w2];
    v.z = tile[j * 4 + 2][w2];
    v.w = tile[j * 4 + 3][w2];
    *(float4*)(g_xp + ((b * Hp + (h + 1)) * Wp + (wblk * 32 + w2 + 1)) * Cc
               + cblk * 32 + j * 4) = v;
}

// ---------------------------------------------------------------------------
// Main fused kernel: 1 block = one (b,h) row of 128 pixels, 256 threads
// Warp tiling: mg = warp>>1 (32 px), nh = warp&1 (N-half)
// ---------------------------------------------------------------------------
__global__ __launch_bounds__(256, 3) void deform_kernel(
    const float* __restrict__ bp, const float* __restrict__ bm,
    float* __restrict__ out) {

    extern __shared__ char sm[];
    float*    As   = (float*)(sm + SM_A);
    uint32_t* AsU  = (uint32_t*)(sm + SM_A);
    uint32_t* BsU  = (uint32_t*)(sm + SM_B);
    float4*   swt4 = (float4*)(sm + SM_SWT);
    int*      sidx = (int*)(sm + SM_SIDX);
    float*    Cst  = (float*)(sm + SM_A);   // staging overlay

    const uint32_t smbA = smem_u32(sm) + SM_A;
    const uint32_t smbB = smem_u32(sm) + SM_B;
    const int tid = threadIdx.x;
    const int warp = tid >> 5, lane = tid & 31;
    const int g = lane >> 2, t4 = lane & 3;
    const int mg = warp >> 1, nh = warp & 1;
    const int px0 = mg * 32;
    const int h = blockIdx.x, b = blockIdx.y;
    const float* __restrict__ xpb = g_xp + b * (Hp * Wp * Cc);

    // ================= Stage 2: offset/mod conv GEMM (M=128,N=32,K=9x64) =====
    float C2[2][2][4];
    #pragma unroll
    for (int mt = 0; mt < 2; mt++)
        #pragma unroll
        for (int nt = 0; nt < 2; nt++)
            #pragma unroll
            for (int r = 0; r < 4; r++) C2[mt][nt][r] = 0.f;

    for (int q = 0; q < 9; q++) {
        const int qy = q / 3, qx = q % 3;
        const float* src = xpb + ((h + qy) * Wp + qx) * Cc;
        #pragma unroll
        for (int r = 0; r < 8; r++) {
            int f = r * 256 + tid;           // 2048 float4
            int px = f >> 4, cg = f & 15;
            cp16(smbA + (px * 64 + 4 * (cg ^ (px & 7))) * 4, src + px * 64 + cg * 4);
        }
        #pragma unroll
        for (int r = 0; r < 2; r++) {
            int f = r * 256 + tid;           // 512 float4
            cp16(smbB + f * 16, g_wb2 + q * 2048 + f * 4);
        }
        asm volatile("cp.async.commit_group;");
        asm volatile("cp.async.wait_group 0;");
        __syncthreads();
        #pragma unroll
        for (int ks = 0; ks < 8; ks++) {
            const int k0 = ks * 8;
            const int sc0 = (k0 + t4) ^ (g << 2);
            const int sc1 = (k0 + t4 + 4) ^ (g << 2);
            #pragma unroll
            for (int mt = 0; mt < 2; mt++) {
                uint32_t a[4];
                int r0 = px0 + mt * 16 + g;
                a[0] = AsU[r0 * 64 + sc0];
                a[1] = AsU[(r0 + 8) * 64 + sc0];
                a[2] = AsU[r0 * 64 + sc1];
                a[3] = AsU[(r0 + 8) * 64 + sc1];
                #pragma unroll
                for (int nt = 0; nt < 2; nt++) {
                    int n = (nh * 2 + nt) * 8 + g;
                    mma8(C2[mt][nt], a, BsU[n * 64 + sc0], BsU[n * 64 + sc1]);
                }
            }
        }
        __syncthreads();
    }
    // stage C2 -> smem [n][132 stride]
    #pragma unroll
    for (int mt = 0; mt < 2; mt++)
        #pragma unroll
        for (int nt = 0; nt < 2; nt++) {
            int n = (nh * 2 + nt) * 8 + 2 * t4;
            int px = px0 + mt * 16 + g;
            if (n < 27)     { Cst[n * 132 + px]       = C2[mt][nt][0];
                              Cst[n * 132 + px + 8]   = C2[mt][nt][2]; }
            if (n + 1 < 27) { Cst[(n + 1) * 132 + px]     = C2[mt][nt][1];
                              Cst[(n + 1) * 132 + px + 8] = C2[mt][nt][3]; }
        }
    __syncthreads();

    // ============ Offsets epilogue: all 256 threads over 1152 tasks ============
    for (int task = tid; task < 1152; task += 256) {
        int px = task / 9, n = task - px * 9;
        float offx = Cst[n * 132 + px]        + bp[n];
        float offy = Cst[(9 + n) * 132 + px]  + bp[9 + n];
        float mz   = Cst[(18 + n) * 132 + px] + bm[n];
        float mm = 1.0f / (1.0f + __expf(-mz));
        int i = n / 3, jj = n % 3;
        float p_x = (float)(h + i) + offx;
        float p_y = (float)(px + jj) + offy;
        float fx = floorf(p_x), fy = floorf(p_y);
        float qltx = fminf(fmaxf(fx,       0.f), 129.f);
        float qlty = fminf(fmaxf(fy,       0.f), 129.f);
        float qrbx = fminf(fmaxf(fx + 1.f, 0.f), 129.f);
        float qrby = fminf(fmaxf(fy + 1.f, 0.f), 129.f);
        float pcx  = fminf(fmaxf(p_x, 0.f), 129.f);
        float pcy  = fminf(fmaxf(p_y, 0.f), 129.f);
        float glt = (1.f + (qltx - pcx)) * (1.f + (qlty - pcy));
        float grb = (1.f - (qrbx - pcx)) * (1.f - (qrby - pcy));
        float glb = (1.f + (qltx - pcx)) * (1.f - (qrby - pcy));
        float grt = (1.f - (qrbx - pcx)) * (1.f + (qlty - pcy));
        int iltx = (int)qltx, ilty = (int)qlty;
        int irbx = (int)qrbx, irby = (int)qrby;
        int base = (iltx * Wp + ilty) * Cc;
        int pack = base | ((irbx - iltx) << 24) | ((irby - ilty) << 25);
        float4 wv;
        wv.x = glt * mm; wv.y = grb * mm; wv.z = glb * mm; wv.w = grt * mm;
        sidx[px * 9 + n] = pack;
        swt4[px * 9 + n] = wv;
    }
    __syncthreads();

    // ============ Stage 5: sample + GEMM (M=128,N=64,K=9x64) ============
    float C5[2][4][4];
    #pragma unroll
    for (int mt = 0; mt < 2; mt++)
        #pragma unroll
        for (int nt = 0; nt < 4; nt++)
            #pragma unroll
            for (int r = 0; r < 4; r++) C5[mt][nt][r] = 0.f;

    const int n0 = nh * 32;
    const int half = lane >> 4;        // which px of the pair
    const int c4 = (lane & 15) * 4;    // channel quad
    for (int n = 0; n < 9; n++) {
        // B tile via cp.async (overlaps with sampling LDGs)
        #pragma unroll
        for (int r = 0; r < 4; r++) {
            int f = r * 256 + tid;
            cp16(smbB + f * 16, g_wb5 + n * 4096 + f * 4);
        }
        asm volatile("cp.async.commit_group;");
        // A tile: float4 bilinear samples (2 px per warp-iteration)
        #pragma unroll
        for (int k = 0; k < 8; k++) {
            int px = warp * 16 + k * 2 + half;
            int si = sidx[px * 9 + n];
            float4 w4 = swt4[px * 9 + n];
            int base = (si & 0xFFFFFF) + c4;
            int dx = (si & (1 << 24)) ? (Wp * Cc) : 0;
            int dy = (si & (1 << 25)) ? Cc : 0;
            float4 t0 = *(const float4*)(xpb + base);
            float4 t1 = *(const float4*)(xpb + base + dx + dy);
            float4 t2 = *(const float4*)(xpb + base + dy);
            float4 t3 = *(const float4*)(xpb + base + dx);
            float4 v;
            v.x = to_tf32(w4.x * t0.x + w4.y * t1.x + w4.z * t2.x + w4.w * t3.x);
            v.y = to_tf32(w4.x * t0.y + w4.y * t1.y + w4.z * t2.y + w4.w * t3.y);
            v.z = to_tf32(w4.x * t0.z + w4.y * t1.z + w4.z * t2.z + w4.w * t3.z);
            v.w = to_tf32(w4.x * t0.w + w4.y * t1.w + w4.z * t2.w + w4.w * t3.w);
            *(float4*)(As + px * 64 + (c4 ^ ((px & 7) << 2))) = v;
        }
        asm volatile("cp.async.wait_group 0;");
        __syncthreads();
        #pragma unroll
        for (int ks = 0; ks < 8; ks++) {
            const int k0 = ks * 8;
            const int sc0 = (k0 + t4) ^ (g << 2);
            const int sc1 = (k0 + t4 + 4) ^ (g << 2);
            #pragma unroll
            for (int mt = 0; mt < 2; mt++) {
                uint32_t a[4];
                int r0 = px0 + mt * 16 + g;
                a[0] = AsU[r0 * 64 + sc0];
                a[1] = AsU[(r0 + 8) * 64 + sc0];
                a[2] = AsU[r0 * 64 + sc1];
                a[3] = AsU[(r0 + 8) * 64 + sc1];
                #pragma unroll
                for (int nt = 0; nt < 4; nt++) {
                    int nn = n0 + nt * 8 + g;
                    mma8(C5[mt][nt], a, BsU[nn * 64 + sc0], BsU[nn * 64 + sc1]);
                }
            }
        }
        __syncthreads();
    }

    // stage C5 -> smem [o][128 stride]
    #pragma unroll
    for (int mt = 0; mt < 2; mt++)
        #pragma unroll
        for (int nt = 0; nt < 4; nt++) {
            int o = n0 + nt * 8 + 2 * t4;
            int px = px0 + mt * 16 + g;
            Cst[o * 128 + px]           = C5[mt][nt][0];
            Cst[(o + 1) * 128 + px]     = C5[mt][nt][1];
            Cst[o * 128 + px + 8]       = C5[mt][nt][2];
            Cst[(o + 1) * 128 + px + 8] = C5[mt][nt][3];
        }
    __syncthreads();

    // coalesced NCHW store
    float* __restrict__ ob = out + (b * Oc * Hc + h) * Wc;
    #pragma unroll
    for (int r = 0; r < 32; r++) {
        int f = r * 256 + tid;
        int o = f >> 7, px = f & 127;
        ob[o * (Hc * Wc) + px] = Cst[o * 128 + px];
    }
}

// ---------------------------------------------------------------------------
extern "C" void kernel_launch(void* const* d_in, const int* in_sizes, int n_in,
                              void* d_out, int out_size) {
    const float* x      = (const float*)d_in[0];
    const float* w_p    = (const float*)d_in[1];
    const float* b_p    = (const float*)d_in[2];
    const float* w_m    = (const float*)d_in[3];
    const float* b_m    = (const float*)d_in[4];
    const float* w_conv = (const float*)d_in[5];
    float* out = (float*)d_out;

    cudaFuncSetAttribute(deform_kernel,
                         cudaFuncAttributeMaxDynamicSharedMemorySize, SM_TOTAL);

    int nprep = Bc * (2 * 130 + 2 * 128) * 64;
    prep_kernel<<<(nprep + 255) / 256, 256>>>(w_p, w_m, w_conv);
    transpose_kernel<<<dim3(4, 128, 8), 256>>>(x);
    deform_kernel<<<dim3(Hc, Bc), 256, SM_TOTAL>>>(b_p, b_m, out);
}

// round 10
// speedup vs baseline: 4.3001x; 1.1328x over previous
#include <cuda_runtime.h>
#include <cstdint>

#define Bc 4
#define Cc 64
#define Hc 128
#define Wc 128
#define Oc 64
#define Hp 130
#define Wp 130

// Device scratch (no allocation allowed)
__device__ float g_xp[Bc * Hp * Wp * Cc];   // padded NHWC x (~16.5 MiB)
__device__ float g_wb2[9 * 32 * 64];        // stage-2 B: [tap q][n 32][c 64] swizzled tf32
__device__ float g_wb5[9 * 64 * 64];        // stage-5 B: [sample n][o 64][c 64] swizzled tf32

__device__ __forceinline__ float to_tf32(float x) {
    float r; asm("cvt.rna.tf32.f32 %0, %1;" : "=f"(r) : "f"(x)); return r;
}
__device__ __forceinline__ uint32_t smem_u32(const void* p) {
    uint32_t a;
    asm("{ .reg .u64 t; cvta.to.shared.u64 t, %1; cvt.u32.u64 %0, t; }" : "=r"(a) : "l"(p));
    return a;
}
__device__ __forceinline__ void cp16(uint32_t dst, const void* src) {
    asm volatile("cp.async.ca.shared.global [%0], [%1], 16;" :: "r"(dst), "l"(src));
}

// m16n8k8 tf32 MMA
__device__ __forceinline__ void mma8(float* c, const uint32_t* a, uint32_t b0, uint32_t b1) {
    asm volatile("mma.sync.aligned.m16n8k8.row.col.f32.tf32.tf32.f32 "
        "{%0,%1,%2,%3}, {%4,%5,%6,%7}, {%8,%9}, {%0,%1,%2,%3};"
        : "+f"(c[0]), "+f"(c[1]), "+f"(c[2]), "+f"(c[3])
        : "r"(a[0]), "r"(a[1]), "r"(a[2]), "r"(a[3]), "r"(b0), "r"(b1));
}

// smem layout (bytes)
#define SM_A     0          /* 130x64 floats = 33280 (pad 33536); C staging overlay */
#define SM_B     33536      /* 3 x 8KB B slots = 24576 (stage5 uses 16KB) */
#define SM_SWT   58112      /* float4[128*9] = 18432 */
#define SM_SIDX  76544      /* int[128*9] = 4608 */
#define SM_TOTAL 81152

// ---------------------------------------------------------------------------
// Fused prep: border zero + weight transposes + NCHW->NHWC transpose
// grid: 516 + 4096 blocks of 256 threads
// ---------------------------------------------------------------------------
__global__ __launch_bounds__(256) void prep_kernel(
    const float* __restrict__ x,
    const float* __restrict__ wp,
    const float* __restrict__ wm,
    const float* __restrict__ wc) {
    if (blockIdx.x < 516) {
        int i = blockIdx.x * 256 + threadIdx.x;
        const int per = (2 * 130 + 2 * 128) * 64;  // 33024
        if (i < Bc * per) {
            int b = i / per, r = i % per;
            int base = b * Hp * Wp * Cc;
            if (r < 130 * 64)            g_xp[base + r] = 0.f;
            else if (r < 2 * 130 * 64)   g_xp[base + 129 * Wp * Cc + (r - 130 * 64)] = 0.f;
            else {
                int t = r - 2 * 130 * 64;
                int which = t / (128 * 64);
                int u = t % (128 * 64);
                int rr = u / 64, c = u % 64;
                int w = which ? 129 : 0;
                g_xp[base + (rr + 1) * Wp * Cc + w * Cc + c] = 0.f;
            }
        }
        if (i < 9 * 32 * 64) {
            int q = i >> 11, rem = i & 2047, n = rem >> 6, c = rem & 63;
            float v = 0.f;
            if (n < 18)      v = wp[n * 576 + c * 9 + q];
            else if (n < 27) v = wm[(n - 18) * 576 + c * 9 + q];
            g_wb2[q * 2048 + n * 64 + (c ^ ((n & 7) << 2))] = to_tf32(v);
        }
        if (i < 9 * 64 * 64) {
            int n = i >> 12, rem = i & 4095, o = rem >> 6, c = rem & 63;
            g_wb5[n * 4096 + o * 64 + (c ^ ((o & 7) << 2))] = to_tf32(wc[o * 576 + c * 9 + n]);
        }
    } else {
        // transpose: bid -> (wblk 0..3, h 0..127, z 0..7)
        int bid = blockIdx.x - 516;
        int wblk = bid & 3, h = (bid >> 2) & 127, z = bid >> 9;
        int b = z >> 1, cblk = z & 1;
        __shared__ float tile[32][33];
        int l = threadIdx.x;
        int tx = l & 31, ty = l >> 5;
        #pragma unroll
        for (int r = 0; r < 4; r++) {
            int c = ty + r * 8;
            tile[c][tx] = x[((b * Cc + cblk * 32 + c) * Hc + h) * Wc + wblk * 32 + tx];
        }
        __syncthreads();
        int j = l & 7, w2 = l >> 3;
        float4 v;
        v.x = tile[j * 4 + 0][w2];
        v.y = tile[j * 4 + 1][w2];
        v.z = tile[j * 4 + 2][w2];
        v.w = tile[j * 4 + 3][w2];
        *(float4*)(g_xp + ((b * Hp + (h + 1)) * Wp + (wblk * 32 + w2 + 1)) * Cc
                   + cblk * 32 + j * 4) = v;
    }
}

// ---------------------------------------------------------------------------
// Main fused kernel: 1 block = one (b,h) row of 128 pixels, 256 threads
// Warp tiling: mg = warp>>1 (32 px), nh = warp&1 (N-half)
// ---------------------------------------------------------------------------
__global__ __launch_bounds__(256, 2) void deform_kernel(
    const float* __restrict__ bp, const float* __restrict__ bm,
    float* __restrict__ out) {

    extern __shared__ char sm[];
    float*    As   = (float*)(sm + SM_A);
    uint32_t* AsU  = (uint32_t*)(sm + SM_A);
    uint32_t* BsU  = (uint32_t*)(sm + SM_B);
    float4*   swt4 = (float4*)(sm + SM_SWT);
    int*      sidx = (int*)(sm + SM_SIDX);
    float*    Cst  = (float*)(sm + SM_A);   // staging overlay

    const uint32_t smbA = smem_u32(sm) + SM_A;
    const uint32_t smbB = smem_u32(sm) + SM_B;
    const int tid = threadIdx.x;
    const int warp = tid >> 5, lane = tid & 31;
    const int g = lane >> 2, t4 = lane & 3;
    const int mg = warp >> 1, nh = warp & 1;
    const int px0 = mg * 32;
    const int h = blockIdx.x, b = blockIdx.y;
    const float* __restrict__ xpb = g_xp + b * (Hp * Wp * Cc);

    // ================= Stage 2: offset/mod conv GEMM (M=128,N=32,K=9x64) =====
    // A row of 130 px loaded once per qy; 3 qx MMA passes read at pixel offset.
    float C2[2][2][4];
    #pragma unroll
    for (int mt = 0; mt < 2; mt++)
        #pragma unroll
        for (int nt = 0; nt < 2; nt++)
            #pragma unroll
            for (int r = 0; r < 4; r++) C2[mt][nt][r] = 0.f;

    for (int qy = 0; qy < 3; qy++) {
        const float* src = xpb + (h + qy) * Wp * Cc;
        // A row: 130 x 64 floats = 2080 float4
        #pragma unroll
        for (int r = 0; r < 9; r++) {
            int f = r * 256 + tid;
            if (f < 2080) {
                int px = f >> 4, cg = f & 15;
                cp16(smbA + (px * 64 + 4 * (cg ^ (px & 7))) * 4, src + px * 64 + cg * 4);
            }
        }
        // 3 B tiles (q = qy*3 + 0..2): 1536 float4
        #pragma unroll
        for (int r = 0; r < 6; r++) {
            int f = r * 256 + tid;
            cp16(smbB + f * 16, g_wb2 + qy * 3 * 2048 + f * 4);
        }
        asm volatile("cp.async.commit_group;");
        asm volatile("cp.async.wait_group 0;");
        __syncthreads();
        #pragma unroll
        for (int qx = 0; qx < 3; qx++) {
            const int gq = (g + qx) & 7;          // = (row & 7) for A rows below
            #pragma unroll
            for (int ks = 0; ks < 8; ks++) {
                const int k0 = ks * 8;
                const int sa0 = (k0 + t4) ^ (gq << 2);
                const int sa1 = (k0 + t4 + 4) ^ (gq << 2);
                const int sb0 = (k0 + t4) ^ (g << 2);
                const int sb1 = (k0 + t4 + 4) ^ (g << 2);
                uint32_t bb[4];
                #pragma unroll
                for (int nt = 0; nt < 2; nt++) {
                    int n = (nh * 2 + nt) * 8 + g;
                    bb[nt * 2]     = BsU[qx * 2048 + n * 64 + sb0];
                    bb[nt * 2 + 1] = BsU[qx * 2048 + n * 64 + sb1];
                }
                #pragma unroll
                for (int mt = 0; mt < 2; mt++) {
                    uint32_t a[4];
                    int r0 = px0 + mt * 16 + g + qx;
                    a[0] = AsU[r0 * 64 + sa0];
                    a[1] = AsU[(r0 + 8) * 64 + sa0];
                    a[2] = AsU[r0 * 64 + sa1];
                    a[3] = AsU[(r0 + 8) * 64 + sa1];
                    #pragma unroll
                    for (int nt = 0; nt < 2; nt++)
                        mma8(C2[mt][nt], a, bb[nt * 2], bb[nt * 2 + 1]);
                }
            }
        }
        __syncthreads();
    }
    // stage C2 -> smem [n][132 stride]
    #pragma unroll
    for (int mt = 0; mt < 2; mt++)
        #pragma unroll
        for (int nt = 0; nt < 2; nt++) {
            int n = (nh * 2 + nt) * 8 + 2 * t4;
            int px = px0 + mt * 16 + g;
            if (n < 27)     { Cst[n * 132 + px]       = C2[mt][nt][0];
                              Cst[n * 132 + px + 8]   = C2[mt][nt][2]; }
            if (n + 1 < 27) { Cst[(n + 1) * 132 + px]     = C2[mt][nt][1];
                              Cst[(n + 1) * 132 + px + 8] = C2[mt][nt][3]; }
        }
    __syncthreads();

    // ============ Offsets epilogue: all 256 threads over 1152 tasks ============
    for (int task = tid; task < 1152; task += 256) {
        int px = task / 9, n = task - px * 9;
        float offx = Cst[n * 132 + px]        + bp[n];
        float offy = Cst[(9 + n) * 132 + px]  + bp[9 + n];
        float mz   = Cst[(18 + n) * 132 + px] + bm[n];
        float mm = 1.0f / (1.0f + __expf(-mz));
        int i = n / 3, jj = n % 3;
        float p_x = (float)(h + i) + offx;
        float p_y = (float)(px + jj) + offy;
        float fx = floorf(p_x), fy = floorf(p_y);
        float qltx = fminf(fmaxf(fx,       0.f), 129.f);
        float qlty = fminf(fmaxf(fy,       0.f), 129.f);
        float qrbx = fminf(fmaxf(fx + 1.f, 0.f), 129.f);
        float qrby = fminf(fmaxf(fy + 1.f, 0.f), 129.f);
        float pcx  = fminf(fmaxf(p_x, 0.f), 129.f);
        float pcy  = fminf(fmaxf(p_y, 0.f), 129.f);
        float glt = (1.f + (qltx - pcx)) * (1.f + (qlty - pcy));
        float grb = (1.f - (qrbx - pcx)) * (1.f - (qrby - pcy));
        float glb = (1.f + (qltx - pcx)) * (1.f - (qrby - pcy));
        float grt = (1.f - (qrbx - pcx)) * (1.f + (qlty - pcy));
        int iltx = (int)qltx, ilty = (int)qlty;
        int irbx = (int)qrbx, irby = (int)qrby;
        int base = (iltx * Wp + ilty) * Cc;
        int pack = base | ((irbx - iltx) << 24) | ((irby - ilty) << 25);
        float4 wv;
        wv.x = glt * mm; wv.y = grb * mm; wv.z = glb * mm; wv.w = grt * mm;
        sidx[px * 9 + n] = pack;
        swt4[px * 9 + n] = wv;
    }
    __syncthreads();

    // ============ Stage 5: sample + GEMM (M=128,N=64,K=9x64) ============
    float C5[2][4][4];
    #pragma unroll
    for (int mt = 0; mt < 2; mt++)
        #pragma unroll
        for (int nt = 0; nt < 4; nt++)
            #pragma unroll
            for (int r = 0; r < 4; r++) C5[mt][nt][r] = 0.f;

    const int n0 = nh * 32;
    const int half = lane >> 4;        // which px of the pair
    const int c4 = (lane & 15) * 4;    // channel quad
    for (int n = 0; n < 9; n++) {
        // B tile via cp.async (overlaps with sampling LDGs)
        #pragma unroll
        for (int r = 0; r < 4; r++) {
            int f = r * 256 + tid;
            cp16(smbB + f * 16, g_wb5 + n * 4096 + f * 4);
        }
        asm volatile("cp.async.commit_group;");
        // A tile: float4 bilinear samples (2 px per warp-iteration)
        #pragma unroll
        for (int k = 0; k < 8; k++) {
            int px = warp * 16 + k * 2 + half;
            int si = sidx[px * 9 + n];
            float4 w4 = swt4[px * 9 + n];
            int base = (si & 0xFFFFFF) + c4;
            int dx = (si & (1 << 24)) ? (Wp * Cc) : 0;
            int dy = (si & (1 << 25)) ? Cc : 0;
            float4 t0 = *(const float4*)(xpb + base);
            float4 t1 = *(const float4*)(xpb + base + dx + dy);
            float4 t2 = *(const float4*)(xpb + base + dy);
            float4 t3 = *(const float4*)(xpb + base + dx);
            float4 v;
            v.x = to_tf32(w4.x * t0.x + w4.y * t1.x + w4.z * t2.x + w4.w * t3.x);
            v.y = to_tf32(w4.x * t0.y + w4.y * t1.y + w4.z * t2.y + w4.w * t3.y);
            v.z = to_tf32(w4.x * t0.z + w4.y * t1.z + w4.z * t2.z + w4.w * t3.z);
            v.w = to_tf32(w4.x * t0.w + w4.y * t1.w + w4.z * t2.w + w4.w * t3.w);
            *(float4*)(As + px * 64 + (c4 ^ ((px & 7) << 2))) = v;
        }
        asm volatile("cp.async.wait_group 0;");
        __syncthreads();
        #pragma unroll
        for (int ks = 0; ks < 8; ks++) {
            const int k0 = ks * 8;
            const int sc0 = (k0 + t4) ^ (g << 2);
            const int sc1 = (k0 + t4 + 4) ^ (g << 2);
            uint32_t bb[8];
            #pragma unroll
            for (int nt = 0; nt < 4; nt++) {
                int nn = n0 + nt * 8 + g;
                bb[nt * 2]     = BsU[nn * 64 + sc0];
                bb[nt * 2 + 1] = BsU[nn * 64 + sc1];
            }
            #pragma unroll
            for (int mt = 0; mt < 2; mt++) {
                uint32_t a[4];
                int r0 = px0 + mt * 16 + g;
                a[0] = AsU[r0 * 64 + sc0];
                a[1] = AsU[(r0 + 8) * 64 + sc0];
                a[2] = AsU[r0 * 64 + sc1];
                a[3] = AsU[(r0 + 8) * 64 + sc1];
                #pragma unroll
                for (int nt = 0; nt < 4; nt++)
                    mma8(C5[mt][nt], a, bb[nt * 2], bb[nt * 2 + 1]);
            }
        }
        __syncthreads();
    }

    // stage C5 -> smem [o][128 stride]
    #pragma unroll
    for (int mt = 0; mt < 2; mt++)
        #pragma unroll
        for (int nt = 0; nt < 4; nt++) {
            int o = n0 + nt * 8 + 2 * t4;
            int px = px0 + mt * 16 + g;
            Cst[o * 128 + px]           = C5[mt][nt][0];
            Cst[(o + 1) * 128 + px]     = C5[mt][nt][1];
            Cst[o * 128 + px + 8]       = C5[mt][nt][2];
            Cst[(o + 1) * 128 + px + 8] = C5[mt][nt][3];
        }
    __syncthreads();

    // coalesced NCHW store
    float* __restrict__ ob = out + (b * Oc * Hc + h) * Wc;
    #pragma unroll
    for (int r = 0; r < 32; r++) {
        int f = r * 256 + tid;
        int o = f >> 7, px = f & 127;
        ob[o * (Hc * Wc) + px] = Cst[o * 128 + px];
    }
}

// ---------------------------------------------------------------------------
extern "C" void kernel_launch(void* const* d_in, const int* in_sizes, int n_in,
                              void* d_out, int out_size) {
    const float* x      = (const float*)d_in[0];
    const float* w_p    = (const float*)d_in[1];
    const float* b_p    = (const float*)d_in[2];
    const float* w_m    = (const float*)d_in[3];
    const float* b_m    = (const float*)d_in[4];
    const float* w_conv = (const float*)d_in[5];
    float* out = (float*)d_out;

    cudaFuncSetAttribute(deform_kernel,
                         cudaFuncAttributeMaxDynamicSharedMemorySize, SM_TOTAL);

    prep_kernel<<<516 + 4096, 256>>>(x, w_p, w_m, w_conv);
    deform_kernel<<<dim3(Hc, Bc), 256, SM_TOTAL>>>(b_p, b_m, out);
}